// round 14
// baseline (speedup 1.0000x reference)
#include <cuda_runtime.h>
#include <math.h>
#include <stdint.h>

#define Bq 4
#define Lq 4096
#define Dq 1024
#define Mq (Bq*Lq)              // 16384 rows
#define CHUNK 128
#define NCHUNK (Lq/CHUNK)       // 32

// ---------------- scratch (static device allocations) ----------------
__device__ float g_xn[(size_t)Mq*Dq];
__device__ float g_y [(size_t)Mq*Dq];
__device__ float g_x1[(size_t)Mq*Dq];
__device__ float g_x2[(size_t)Mq*Dq];
__device__ float g_c [(size_t)Mq*Dq];
__device__ float g_v [(size_t)Mq*Dq];
__device__ float g_hg[(size_t)Mq*2*Dq];
__device__ float g_h4[(size_t)Mq*4*Dq];
__device__ float g_Hc[Bq*NCHUNK*Dq];
__device__ float g_Cc[Bq*NCHUNK*Dq];
__device__ float g_Hi[Bq*NCHUNK*Dq];

// ---------------- rmsnorm ----------------
__global__ __launch_bounds__(256) void rmsnorm_k(const float* __restrict__ x,
                                                 const float* __restrict__ g,
                                                 float* __restrict__ out)
{
    const int row = blockIdx.x;
    const int tid = threadIdx.x;
    const float4* xr = (const float4*)(x + (size_t)row * Dq);
    float4 xv = xr[tid];
    float s = xv.x*xv.x + xv.y*xv.y + xv.z*xv.z + xv.w*xv.w;
    #pragma unroll
    for (int o = 16; o > 0; o >>= 1) s += __shfl_xor_sync(0xffffffffu, s, o);
    __shared__ float red[8];
    if ((tid & 31) == 0) red[tid >> 5] = s;
    __syncthreads();
    if (tid < 32) {
        float t2 = (tid < 8) ? red[tid] : 0.f;
        #pragma unroll
        for (int o = 4; o > 0; o >>= 1) t2 += __shfl_xor_sync(0xffffffffu, t2, o);
        if (tid == 0) red[0] = t2;
    }
    __syncthreads();
    float inv = 32.0f / fmaxf(sqrtf(red[0]), 1e-12f);
    const float4 gv = ((const float4*)g)[tid];
    float4 o4;
    o4.x = xv.x * inv * (gv.x + 1.f);
    o4.y = xv.y * inv * (gv.y + 1.f);
    o4.z = xv.z * inv * (gv.z + 1.f);
    o4.w = xv.w * inv * (gv.w + 1.f);
    ((float4*)(out + (size_t)row * Dq))[tid] = o4;
}

// ---------------- fused rmsnorm + causal dwconv(K=3) + bias -> g_y ----------------
__global__ __launch_bounds__(256) void rmsnorm_dwconv_k(const float* __restrict__ x,
                                                        const float* __restrict__ g,
                                                        const float* __restrict__ wdw,
                                                        const float* __restrict__ bdw)
{
    const int row = blockIdx.x;
    const int tid = threadIdx.x;
    const int l = row % Lq;

    float4 xv0 = ((const float4*)(x + (size_t)row * Dq))[tid];
    float4 xv1 = make_float4(0.f,0.f,0.f,0.f);
    float4 xv2 = make_float4(0.f,0.f,0.f,0.f);
    if (l >= 1) xv1 = ((const float4*)(x + (size_t)(row-1) * Dq))[tid];
    if (l >= 2) xv2 = ((const float4*)(x + (size_t)(row-2) * Dq))[tid];

    float s0 = xv0.x*xv0.x + xv0.y*xv0.y + xv0.z*xv0.z + xv0.w*xv0.w;
    float s1 = xv1.x*xv1.x + xv1.y*xv1.y + xv1.z*xv1.z + xv1.w*xv1.w;
    float s2 = xv2.x*xv2.x + xv2.y*xv2.y + xv2.z*xv2.z + xv2.w*xv2.w;
    #pragma unroll
    for (int o = 16; o > 0; o >>= 1) {
        s0 += __shfl_xor_sync(0xffffffffu, s0, o);
        s1 += __shfl_xor_sync(0xffffffffu, s1, o);
        s2 += __shfl_xor_sync(0xffffffffu, s2, o);
    }
    __shared__ float red0[8], red1[8], red2[8], invs[3];
    if ((tid & 31) == 0) { red0[tid>>5]=s0; red1[tid>>5]=s1; red2[tid>>5]=s2; }
    __syncthreads();
    if (tid < 32) {
        float t0 = (tid < 8) ? red0[tid] : 0.f;
        float t1 = (tid < 8) ? red1[tid] : 0.f;
        float t2 = (tid < 8) ? red2[tid] : 0.f;
        #pragma unroll
        for (int o = 4; o > 0; o >>= 1) {
            t0 += __shfl_xor_sync(0xffffffffu, t0, o);
            t1 += __shfl_xor_sync(0xffffffffu, t1, o);
            t2 += __shfl_xor_sync(0xffffffffu, t2, o);
        }
        if (tid == 0) {
            invs[0] = 32.0f / fmaxf(sqrtf(t0), 1e-12f);
            invs[1] = 32.0f / fmaxf(sqrtf(t1), 1e-12f);
            invs[2] = 32.0f / fmaxf(sqrtf(t2), 1e-12f);
        }
    }
    __syncthreads();
    const float inv0 = invs[0], inv1 = invs[1], inv2 = invs[2];
    const float4 gv = ((const float4*)g)[tid];
    const float4* wp = (const float4*)(wdw + tid*12);   // 4 channels x 3 taps
    float4 w4a = wp[0], w4b = wp[1], w4c = wp[2];
    const float4 bd = ((const float4*)bdw)[tid];
    float4 y;
    y.x = bd.x + w4a.z*(xv0.x*inv0*(gv.x+1.f)) + w4a.y*(xv1.x*inv1*(gv.x+1.f)) + w4a.x*(xv2.x*inv2*(gv.x+1.f));
    y.y = bd.y + w4b.y*(xv0.y*inv0*(gv.y+1.f)) + w4b.x*(xv1.y*inv1*(gv.y+1.f)) + w4a.w*(xv2.y*inv2*(gv.y+1.f));
    y.z = bd.z + w4c.x*(xv0.z*inv0*(gv.z+1.f)) + w4b.w*(xv1.z*inv1*(gv.z+1.f)) + w4b.z*(xv2.z*inv2*(gv.z+1.f));
    y.w = bd.w + w4c.w*(xv0.w*inv0*(gv.w+1.f)) + w4c.z*(xv1.w*inv1*(gv.w+1.f)) + w4c.y*(xv2.w*inv2*(gv.w+1.f));
    ((float4*)(g_y + (size_t)row * Dq))[tid] = y;
}

// ---------------- fp16 tensor-core NT GEMM (fp32 accum), 2-stage pipeline ----------------
// 512 threads, 16 warps, warp tile 32x32, block tile 128x128xBK32.
// C[M,N] = A[M,K] * B[N,K]^T ; m16n8k16 fragments stored in frag order.
// MODE 0/3: +bias +res ; MODE 1: plain ; MODE 2: +bias exact gelu
__device__ __forceinline__ uint32_t f32x2_h2(float lo, float hi) {
    uint32_t r;
    asm("cvt.rn.f16x2.f32 %0, %1, %2;" : "=r"(r) : "f"(hi), "f"(lo));
    return r;
}
__device__ __forceinline__ void mma_f16(float* c, const uint32_t* a, const uint32_t* b) {
    asm volatile(
        "mma.sync.aligned.m16n8k16.row.col.f32.f16.f16.f32 "
        "{%0,%1,%2,%3}, {%4,%5,%6,%7}, {%8,%9}, {%0,%1,%2,%3};"
        : "+f"(c[0]), "+f"(c[1]), "+f"(c[2]), "+f"(c[3])
        : "r"(a[0]), "r"(a[1]), "r"(a[2]), "r"(a[3]), "r"(b[0]), "r"(b[1]));
}

template<int MODE>
__global__ __launch_bounds__(512) void gemm_tc(
    const float* __restrict__ A, const float* __restrict__ Bm,
    const float* __restrict__ bias, const float* __restrict__ res,
    float* __restrict__ C, int N_, int K_)
{
    __shared__ __align__(16) uint32_t As[2][2048];   // 128 x 32 f16 frag order
    __shared__ __align__(16) uint32_t Bs[2][2048];

    const int tid  = threadIdx.x;
    const int lane = tid & 31;
    const int g    = lane >> 2;
    const int t    = lane & 3;
    const int wid  = tid >> 5;         // 0..15
    const int wm2  = (wid >> 2) * 2;   // mrow base (2 mrows = 32 rows)
    const int wn4  = (wid & 3) * 4;    // ngrp base (4 ngrps = 32 cols)
    const int bm   = blockIdx.y * 128;
    const int bn   = blockIdx.x * 128;

    // loader: 512 thr, 2 passes of 64 rows, 8 float4/row
    const int lrow = tid >> 3;         // 0..63
    const int lkc  = (tid & 7) << 2;   // 0..28
    const int kk_s  = lkc >> 4;
    const int kin   = lkc & 15;
    const int khi_s = kin >> 3;
    const int tb_s  = (kin & 7) >> 1;

    int abase_[2], bbase_[2];
    #pragma unroll
    for (int p = 0; p < 2; p++) {
        int row  = p*64 + lrow;
        int mrow = row >> 4;
        int ri   = row & 15;
        abase_[p] = ((mrow*2 + kk_s)*8 + (ri & 7))*16 + ((ri >> 3) + khi_s*2);
        bbase_[p] = (((row >> 3)*2 + kk_s)*8 + (row & 7))*8 + khi_s;
    }
    const int tpa0 = ((tb_s  ) ^ kk_s)*4, tpa1 = ((tb_s+1) ^ kk_s)*4;
    const int tpb0 = ((tb_s  ) ^ kk_s)*2, tpb1 = ((tb_s+1) ^ kk_s)*2;

    float acc[2][4][4];
    #pragma unroll
    for (int mi = 0; mi < 2; mi++)
        #pragma unroll
        for (int ni = 0; ni < 4; ni++)
            #pragma unroll
            for (int r = 0; r < 4; r++) acc[mi][ni][r] = 0.f;

    float4 pa[2], pb[2];
    const int niter = K_ >> 5;

    // preload iter 0 -> regs -> stage 0
    #pragma unroll
    for (int p = 0; p < 2; p++) {
        int row = p*64 + lrow;
        pa[p] = *(const float4*)(A  + (size_t)(bm + row) * K_ + lkc);
        pb[p] = *(const float4*)(Bm + (size_t)(bn + row) * K_ + lkc);
    }
    #pragma unroll
    for (int p = 0; p < 2; p++) {
        As[0][abase_[p] + tpa0] = f32x2_h2(pa[p].x, pa[p].y);
        As[0][abase_[p] + tpa1] = f32x2_h2(pa[p].z, pa[p].w);
        Bs[0][bbase_[p] + tpb0] = f32x2_h2(pb[p].x, pb[p].y);
        Bs[0][bbase_[p] + tpb1] = f32x2_h2(pb[p].z, pb[p].w);
    }
    // preload iter 1 -> regs
    if (niter > 1) {
        #pragma unroll
        for (int p = 0; p < 2; p++) {
            int row = p*64 + lrow;
            pa[p] = *(const float4*)(A  + (size_t)(bm + row) * K_ + 32 + lkc);
            pb[p] = *(const float4*)(Bm + (size_t)(bn + row) * K_ + 32 + lkc);
        }
    }
    __syncthreads();

    for (int it = 0; it < niter; it++) {
        const int s = it & 1;
        if (it + 1 < niter) {
            #pragma unroll
            for (int p = 0; p < 2; p++) {
                As[s^1][abase_[p] + tpa0] = f32x2_h2(pa[p].x, pa[p].y);
                As[s^1][abase_[p] + tpa1] = f32x2_h2(pa[p].z, pa[p].w);
                Bs[s^1][bbase_[p] + tpb0] = f32x2_h2(pb[p].x, pb[p].y);
                Bs[s^1][bbase_[p] + tpb1] = f32x2_h2(pb[p].z, pb[p].w);
            }
        }
        if (it + 2 < niter) {
            int k0 = (it + 2) << 5;
            #pragma unroll
            for (int p = 0; p < 2; p++) {
                int row = p*64 + lrow;
                pa[p] = *(const float4*)(A  + (size_t)(bm + row) * K_ + k0 + lkc);
                pb[p] = *(const float4*)(Bm + (size_t)(bn + row) * K_ + k0 + lkc);
            }
        }
        #pragma unroll
        for (int kk = 0; kk < 2; kk++) {
            const int tp = t ^ kk;
            uint4 af[2];
            #pragma unroll
            for (int mi = 0; mi < 2; mi++)
                af[mi] = *(const uint4*)&As[s][(((wm2 + mi)*2 + kk)*8 + g)*16 + tp*4];
            uint2 bf[4];
            #pragma unroll
            for (int ni = 0; ni < 4; ni++)
                bf[ni] = *(const uint2*)&Bs[s][(((wn4 + ni)*2 + kk)*8 + g)*8 + tp*2];
            #pragma unroll
            for (int mi = 0; mi < 2; mi++)
                #pragma unroll
                for (int ni = 0; ni < 4; ni++)
                    mma_f16(acc[mi][ni], (const uint32_t*)&af[mi], (const uint32_t*)&bf[ni]);
        }
        __syncthreads();
    }

    // ---------------- epilogue ----------------
    #pragma unroll
    for (int mi = 0; mi < 2; mi++) {
        #pragma unroll
        for (int ni = 0; ni < 4; ni++) {
            int row0 = bm + (wm2 + mi)*16 + g;
            int col  = bn + (wn4 + ni)*8 + 2*t;
            #pragma unroll
            for (int h = 0; h < 2; h++) {
                int row = row0 + h*8;
                float v0 = acc[mi][ni][2*h + 0];
                float v1 = acc[mi][ni][2*h + 1];
                if (MODE == 0 || MODE == 3) {
                    v0 += bias[col]   + res[(size_t)row * N_ + col];
                    v1 += bias[col+1] + res[(size_t)row * N_ + col + 1];
                } else if (MODE == 2) {
                    v0 += bias[col];
                    v1 += bias[col+1];
                    v0 = 0.5f * v0 * (1.f + erff(v0 * 0.70710678118654752f));
                    v1 = 0.5f * v1 * (1.f + erff(v1 * 0.70710678118654752f));
                }
                *(float2*)(C + (size_t)row * N_ + col) = make_float2(v0, v1);
            }
        }
    }
}

// ---------------- minGRU chunked scan ----------------
__global__ __launch_bounds__(256) void scan1_k(const float* __restrict__ hg)
{
    int d  = blockIdx.x * 256 + threadIdx.x;
    int ch = blockIdx.y;
    int b  = blockIdx.z;
    size_t row0 = (size_t)b * Lq + (size_t)ch * CHUNK;
    float h = 0.f, cp = 1.f;
    for (int t = 0; t < CHUNK; t++) {
        size_t r = row0 + t;
        float hd = hg[r*2*Dq + d];
        float gg = hg[r*2*Dq + Dq + d];
        float sp = fmaxf(gg, 0.f) + log1pf(expf(-fabsf(gg)));
        float lg = (hd >= 0.f) ? logf(hd + 0.5f) : (hd - log1pf(expf(hd)));
        float c = expf(-sp);
        float v = expf(gg - sp + lg);
        g_c[r*Dq + d] = c;
        g_v[r*Dq + d] = v;
        h = fmaf(c, h, v);
        cp *= c;
    }
    int sidx = (b*NCHUNK + ch)*Dq + d;
    g_Hc[sidx] = h;
    g_Cc[sidx] = cp;
}

__global__ __launch_bounds__(256) void scan2_k()
{
    int d = blockIdx.x * 256 + threadIdx.x;
    int b = blockIdx.z;
    float h = 0.f;
    for (int ch = 0; ch < NCHUNK; ch++) {
        int sidx = (b*NCHUNK + ch)*Dq + d;
        g_Hi[sidx] = h;
        h = fmaf(g_Cc[sidx], h, g_Hc[sidx]);
    }
}

__global__ __launch_bounds__(256) void scan3_k(const float* __restrict__ x1,
                                               float* __restrict__ x2,
                                               float* __restrict__ nh)
{
    int d  = blockIdx.x * 256 + threadIdx.x;
    int ch = blockIdx.y;
    int b  = blockIdx.z;
    size_t row0 = (size_t)b * Lq + (size_t)ch * CHUNK;
    float h = g_Hi[(b*NCHUNK + ch)*Dq + d];
    for (int t = 0; t < CHUNK; t++) {
        size_t r = row0 + t;
        h = fmaf(g_c[r*Dq + d], h, g_v[r*Dq + d]);
        x2[r*Dq + d] = h + x1[r*Dq + d];
    }
    if (ch == NCHUNK - 1) nh[b*Dq + d] = h;
}

// ---------------- launch ----------------
extern "C" void kernel_launch(void* const* d_in, const int* in_sizes, int n_in,
                              void* d_out, int out_size)
{
    const float* x           = (const float*)d_in[0];
    const float* conv_dw_w   = (const float*)d_in[1];
    const float* conv_dw_b   = (const float*)d_in[2];
    const float* conv_pw_w   = (const float*)d_in[3];
    const float* conv_pw_b   = (const float*)d_in[4];
    const float* conv_norm_g = (const float*)d_in[5];
    const float* gru_norm_g  = (const float*)d_in[6];
    const float* gru_w       = (const float*)d_in[7];
    const float* ff_norm_g   = (const float*)d_in[8];
    const float* ff_w1       = (const float*)d_in[9];
    const float* ff_b1       = (const float*)d_in[10];
    const float* ff_w2       = (const float*)d_in[11];
    const float* ff_b2       = (const float*)d_in[12];
    float* out = (float*)d_out;

    float *xn, *y, *x1, *x2, *hg, *h4;
    cudaGetSymbolAddress((void**)&xn, g_xn);
    cudaGetSymbolAddress((void**)&y,  g_y);
    cudaGetSymbolAddress((void**)&x1, g_x1);
    cudaGetSymbolAddress((void**)&x2, g_x2);
    cudaGetSymbolAddress((void**)&hg, g_hg);
    cudaGetSymbolAddress((void**)&h4, g_h4);

    // 1) conv block (fused rmsnorm+dwconv)
    rmsnorm_dwconv_k<<<Mq, 256>>>(x, conv_norm_g, conv_dw_w, conv_dw_b);
    gemm_tc<0><<<dim3(Dq/128, Mq/128), 512>>>(y, conv_pw_w, conv_pw_b, x, x1, Dq, Dq);

    // 2) gru block
    rmsnorm_k<<<Mq, 256>>>(x1, gru_norm_g, xn);
    gemm_tc<1><<<dim3(2*Dq/128, Mq/128), 512>>>(xn, gru_w, nullptr, nullptr, hg, 2*Dq, Dq);
    scan1_k<<<dim3(Dq/256, NCHUNK, Bq), 256>>>(hg);
    scan2_k<<<dim3(Dq/256, 1, Bq), 256>>>();
    scan3_k<<<dim3(Dq/256, NCHUNK, Bq), 256>>>(x1, x2, out + (size_t)Mq*Dq);

    // 3) ff block
    rmsnorm_k<<<Mq, 256>>>(x2, ff_norm_g, xn);
    gemm_tc<2><<<dim3(4*Dq/128, Mq/128), 512>>>(xn, ff_w1, ff_b1, nullptr, h4, 4*Dq, Dq);
    gemm_tc<3><<<dim3(Dq/128, Mq/128), 512>>>(h4, ff_w2, ff_b2, x2, out, Dq, 4*Dq);
}

// round 16
// speedup vs baseline: 3.0327x; 3.0327x over previous
#include <cuda_runtime.h>
#include <cuda_fp16.h>
#include <math.h>
#include <stdint.h>

#define Bq 4
#define Lq 4096
#define Dq 1024
#define Mq (Bq*Lq)              // 16384 rows
#define CHUNK 128
#define NCHUNK (Lq/CHUNK)       // 32

// ---------------- scratch (static device allocations) ----------------
__device__ __align__(256) float g_xn[(size_t)Mq*Dq];   // reused as half buffer
__device__ __align__(256) float g_y [(size_t)Mq*Dq];   // reused as half buffer
__device__ __align__(256) float g_x1[(size_t)Mq*Dq];
__device__ __align__(256) float g_x2[(size_t)Mq*Dq];
__device__ __align__(256) float g_c [(size_t)Mq*Dq];
__device__ __align__(256) float g_v [(size_t)Mq*Dq];
__device__ __align__(256) float g_hg[(size_t)Mq*2*Dq];
__device__ __align__(256) float g_h4[(size_t)Mq*4*Dq]; // reused as half buffer
__device__ __align__(256) __half g_wh[11534336];       // fp16 weights: pw|gru|w1|w2
__device__ float g_Hc[Bq*NCHUNK*Dq];
__device__ float g_Cc[Bq*NCHUNK*Dq];
__device__ float g_Hi[Bq*NCHUNK*Dq];

// ---------------- f32 -> f16 weight conversion ----------------
__global__ __launch_bounds__(256) void f2h_k(const float4* __restrict__ in,
                                             uint2* __restrict__ out, int n4)
{
    int i = blockIdx.x * 256 + threadIdx.x;
    if (i >= n4) return;
    float4 v = in[i];
    __half2 h0 = __floats2half2_rn(v.x, v.y);
    __half2 h1 = __floats2half2_rn(v.z, v.w);
    out[i] = make_uint2(*(uint32_t*)&h0, *(uint32_t*)&h1);
}

// ---------------- rmsnorm (fp16 output) ----------------
__global__ __launch_bounds__(256) void rmsnorm_h_k(const float* __restrict__ x,
                                                   const float* __restrict__ g,
                                                   __half* __restrict__ out)
{
    const int row = blockIdx.x;
    const int tid = threadIdx.x;
    const float4* xr = (const float4*)(x + (size_t)row * Dq);
    float4 xv = xr[tid];
    float s = xv.x*xv.x + xv.y*xv.y + xv.z*xv.z + xv.w*xv.w;
    #pragma unroll
    for (int o = 16; o > 0; o >>= 1) s += __shfl_xor_sync(0xffffffffu, s, o);
    __shared__ float red[8];
    if ((tid & 31) == 0) red[tid >> 5] = s;
    __syncthreads();
    if (tid < 32) {
        float t2 = (tid < 8) ? red[tid] : 0.f;
        #pragma unroll
        for (int o = 4; o > 0; o >>= 1) t2 += __shfl_xor_sync(0xffffffffu, t2, o);
        if (tid == 0) red[0] = t2;
    }
    __syncthreads();
    float inv = 32.0f / fmaxf(sqrtf(red[0]), 1e-12f);
    const float4 gv = ((const float4*)g)[tid];
    __half2 h0 = __floats2half2_rn(xv.x * inv * (gv.x + 1.f), xv.y * inv * (gv.y + 1.f));
    __half2 h1 = __floats2half2_rn(xv.z * inv * (gv.z + 1.f), xv.w * inv * (gv.w + 1.f));
    ((uint2*)(out + (size_t)row * Dq))[tid] = make_uint2(*(uint32_t*)&h0, *(uint32_t*)&h1);
}

// ---------------- fused rmsnorm + causal dwconv(K=3) + bias -> fp16 y ----------------
__global__ __launch_bounds__(256) void rmsnorm_dwconv_k(const float* __restrict__ x,
                                                        const float* __restrict__ g,
                                                        const float* __restrict__ wdw,
                                                        const float* __restrict__ bdw,
                                                        __half* __restrict__ yh)
{
    const int row = blockIdx.x;
    const int tid = threadIdx.x;
    const int l = row % Lq;

    float4 xv0 = ((const float4*)(x + (size_t)row * Dq))[tid];
    float4 xv1 = make_float4(0.f,0.f,0.f,0.f);
    float4 xv2 = make_float4(0.f,0.f,0.f,0.f);
    if (l >= 1) xv1 = ((const float4*)(x + (size_t)(row-1) * Dq))[tid];
    if (l >= 2) xv2 = ((const float4*)(x + (size_t)(row-2) * Dq))[tid];

    float s0 = xv0.x*xv0.x + xv0.y*xv0.y + xv0.z*xv0.z + xv0.w*xv0.w;
    float s1 = xv1.x*xv1.x + xv1.y*xv1.y + xv1.z*xv1.z + xv1.w*xv1.w;
    float s2 = xv2.x*xv2.x + xv2.y*xv2.y + xv2.z*xv2.z + xv2.w*xv2.w;
    #pragma unroll
    for (int o = 16; o > 0; o >>= 1) {
        s0 += __shfl_xor_sync(0xffffffffu, s0, o);
        s1 += __shfl_xor_sync(0xffffffffu, s1, o);
        s2 += __shfl_xor_sync(0xffffffffu, s2, o);
    }
    __shared__ float red0[8], red1[8], red2[8], invs[3];
    if ((tid & 31) == 0) { red0[tid>>5]=s0; red1[tid>>5]=s1; red2[tid>>5]=s2; }
    __syncthreads();
    if (tid < 32) {
        float t0 = (tid < 8) ? red0[tid] : 0.f;
        float t1 = (tid < 8) ? red1[tid] : 0.f;
        float t2 = (tid < 8) ? red2[tid] : 0.f;
        #pragma unroll
        for (int o = 4; o > 0; o >>= 1) {
            t0 += __shfl_xor_sync(0xffffffffu, t0, o);
            t1 += __shfl_xor_sync(0xffffffffu, t1, o);
            t2 += __shfl_xor_sync(0xffffffffu, t2, o);
        }
        if (tid == 0) {
            invs[0] = 32.0f / fmaxf(sqrtf(t0), 1e-12f);
            invs[1] = 32.0f / fmaxf(sqrtf(t1), 1e-12f);
            invs[2] = 32.0f / fmaxf(sqrtf(t2), 1e-12f);
        }
    }
    __syncthreads();
    const float inv0 = invs[0], inv1 = invs[1], inv2 = invs[2];
    const float4 gv = ((const float4*)g)[tid];
    const float4* wp = (const float4*)(wdw + tid*12);
    float4 w4a = wp[0], w4b = wp[1], w4c = wp[2];
    const float4 bd = ((const float4*)bdw)[tid];
    float4 y;
    y.x = bd.x + w4a.z*(xv0.x*inv0*(gv.x+1.f)) + w4a.y*(xv1.x*inv1*(gv.x+1.f)) + w4a.x*(xv2.x*inv2*(gv.x+1.f));
    y.y = bd.y + w4b.y*(xv0.y*inv0*(gv.y+1.f)) + w4b.x*(xv1.y*inv1*(gv.y+1.f)) + w4a.w*(xv2.y*inv2*(gv.y+1.f));
    y.z = bd.z + w4c.x*(xv0.z*inv0*(gv.z+1.f)) + w4b.w*(xv1.z*inv1*(gv.z+1.f)) + w4b.z*(xv2.z*inv2*(gv.z+1.f));
    y.w = bd.w + w4c.w*(xv0.w*inv0*(gv.w+1.f)) + w4c.z*(xv1.w*inv1*(gv.w+1.f)) + w4c.y*(xv2.w*inv2*(gv.w+1.f));
    __half2 h0 = __floats2half2_rn(y.x, y.y);
    __half2 h1 = __floats2half2_rn(y.z, y.w);
    ((uint2*)(yh + (size_t)row * Dq))[tid] = make_uint2(*(uint32_t*)&h0, *(uint32_t*)&h1);
}

// ---------------- fp16 GEMM: cp.async 3-stage + ldmatrix + m16n8k16 ----------------
// C[M,N] = A[M,K] * B[N,K]^T, A/B fp16 in gmem, fp32 accum.
// 256 thr, 8 warps, warp tile 64x32, block 128x128, BK=32, STAGES=3.
// MODE 0/3: +bias +res -> f32 C ; MODE 1: plain -> f32 C ; MODE 2: +bias gelu -> f16 Ch
#define CPA(dst, src) asm volatile("cp.async.cg.shared.global [%0], [%1], 16;\n" :: "r"(dst), "l"(src))
#define CPC()         asm volatile("cp.async.commit_group;\n" ::: "memory")
#define CPW(n)        asm volatile("cp.async.wait_group %0;\n" :: "n"(n) : "memory")
__device__ __forceinline__ void mma_f16(float* c, const uint32_t* a, const uint32_t* b) {
    asm volatile(
        "mma.sync.aligned.m16n8k16.row.col.f32.f16.f16.f32 "
        "{%0,%1,%2,%3}, {%4,%5,%6,%7}, {%8,%9}, {%0,%1,%2,%3};"
        : "+f"(c[0]), "+f"(c[1]), "+f"(c[2]), "+f"(c[3])
        : "r"(a[0]), "r"(a[1]), "r"(a[2]), "r"(a[3]), "r"(b[0]), "r"(b[1]));
}

template<int MODE>
__global__ __launch_bounds__(256, 2) void gemm_tc(
    const __half* __restrict__ A, const __half* __restrict__ Bm,
    const float* __restrict__ bias, const float* __restrict__ res,
    float* __restrict__ C, __half* __restrict__ Ch, int N_, int K_)
{
    __shared__ __align__(1024) char smem[3*16384];   // stage: A 8KB | B 8KB

    const int tid  = threadIdx.x;
    const int lane = tid & 31;
    const int g    = lane >> 2;
    const int t    = lane & 3;
    const int wid  = tid >> 5;
    const int wm4  = (wid >> 2) * 4;   // 4 m16 tiles
    const int wn4  = (wid & 3) * 4;    // 4 n8 tiles
    const int bm   = blockIdx.y * 128;
    const int bn   = blockIdx.x * 128;
    const uint32_t sb = (uint32_t)__cvta_generic_to_shared(smem);

    // cp.async loader: chunk ci (0..511): row=ci>>2, c16=ci&3
    int arow[2], ac16[2], adst[2];
    #pragma unroll
    for (int p = 0; p < 2; p++) {
        int ci = tid + p*256;
        arow[p] = ci >> 2;
        ac16[p] = ci & 3;
        adst[p] = arow[p]*64 + ((ac16[p] ^ ((arow[p]>>1)&3)) << 4);
    }

    // ldmatrix lane-invariant parts
    const int lar = lane & 15;                 // A tile row
    const int lac = lane >> 4;                 // A k-half
    const int pa_ = (lar >> 1) & 3;
    const int lbr = lane & 7;                  // B tile row
    const int lbc = (lane >> 3) & 1;           // B k-half
    const int pb_ = (lbr >> 1) & 3;

    float acc[4][4][4];
    #pragma unroll
    for (int mi = 0; mi < 4; mi++)
        #pragma unroll
        for (int ni = 0; ni < 4; ni++)
            #pragma unroll
            for (int r = 0; r < 4; r++) acc[mi][ni][r] = 0.f;

    const int niter = K_ >> 5;

    // prologue: stages 0,1
    #pragma unroll
    for (int st = 0; st < 2; st++) {
        int k0 = st << 5;
        #pragma unroll
        for (int p = 0; p < 2; p++) {
            CPA(sb + st*16384 + adst[p],
                A + (size_t)(bm + arow[p]) * K_ + k0 + ac16[p]*8);
            CPA(sb + st*16384 + 8192 + adst[p],
                Bm + (size_t)(bn + arow[p]) * K_ + k0 + ac16[p]*8);
        }
        CPC();
    }

    for (int it = 0; it < niter; it++) {
        const int s = it - (it/3)*3;
        CPW(1);
        __syncthreads();
        if (it + 2 < niter) {
            int s2 = (it+2) - ((it+2)/3)*3;
            int k0 = (it + 2) << 5;
            #pragma unroll
            for (int p = 0; p < 2; p++) {
                CPA(sb + s2*16384 + adst[p],
                    A + (size_t)(bm + arow[p]) * K_ + k0 + ac16[p]*8);
                CPA(sb + s2*16384 + 8192 + adst[p],
                    Bm + (size_t)(bn + arow[p]) * K_ + k0 + ac16[p]*8);
            }
        }
        CPC();

        const uint32_t abase = sb + s*16384;
        const uint32_t bbase = abase + 8192;
        #pragma unroll
        for (int kk = 0; kk < 2; kk++) {
            const int ca = ((kk*2 + lac) ^ pa_) << 4;
            const int cb = ((kk*2 + lbc) ^ pb_) << 4;
            uint32_t af[4][4];
            #pragma unroll
            for (int mi = 0; mi < 4; mi++) {
                uint32_t ad = abase + (wm4 + mi)*1024 + lar*64 + ca;
                asm volatile("ldmatrix.sync.aligned.m8n8.x4.shared.b16 {%0,%1,%2,%3}, [%4];"
                    : "=r"(af[mi][0]), "=r"(af[mi][1]), "=r"(af[mi][2]), "=r"(af[mi][3])
                    : "r"(ad));
            }
            uint32_t bf[4][2];
            #pragma unroll
            for (int ni = 0; ni < 4; ni++) {
                uint32_t bd = bbase + (wn4 + ni)*512 + lbr*64 + cb;
                asm volatile("ldmatrix.sync.aligned.m8n8.x2.shared.b16 {%0,%1}, [%2];"
                    : "=r"(bf[ni][0]), "=r"(bf[ni][1])
                    : "r"(bd));
            }
            #pragma unroll
            for (int mi = 0; mi < 4; mi++)
                #pragma unroll
                for (int ni = 0; ni < 4; ni++)
                    mma_f16(acc[mi][ni], af[mi], bf[ni]);
        }
        __syncthreads();
    }

    // ---------------- epilogue ----------------
    #pragma unroll
    for (int mi = 0; mi < 4; mi++) {
        #pragma unroll
        for (int ni = 0; ni < 4; ni++) {
            int row0 = bm + (wm4 + mi)*16 + g;
            int col  = bn + (wn4 + ni)*8 + 2*t;
            #pragma unroll
            for (int h = 0; h < 2; h++) {
                int row = row0 + h*8;
                float v0 = acc[mi][ni][2*h + 0];
                float v1 = acc[mi][ni][2*h + 1];
                if (MODE == 0 || MODE == 3) {
                    v0 += bias[col]   + res[(size_t)row * N_ + col];
                    v1 += bias[col+1] + res[(size_t)row * N_ + col + 1];
                    *(float2*)(C + (size_t)row * N_ + col) = make_float2(v0, v1);
                } else if (MODE == 2) {
                    v0 += bias[col];
                    v1 += bias[col+1];
                    v0 = 0.5f * v0 * (1.f + erff(v0 * 0.70710678118654752f));
                    v1 = 0.5f * v1 * (1.f + erff(v1 * 0.70710678118654752f));
                    __half2 hv = __floats2half2_rn(v0, v1);
                    *(uint32_t*)(Ch + (size_t)row * N_ + col) = *(uint32_t*)&hv;
                } else {
                    *(float2*)(C + (size_t)row * N_ + col) = make_float2(v0, v1);
                }
            }
        }
    }
}

// ---------------- minGRU chunked scan ----------------
__global__ __launch_bounds__(256) void scan1_k(const float* __restrict__ hg)
{
    int d  = blockIdx.x * 256 + threadIdx.x;
    int ch = blockIdx.y;
    int b  = blockIdx.z;
    size_t row0 = (size_t)b * Lq + (size_t)ch * CHUNK;
    float h = 0.f, cp = 1.f;
    for (int t = 0; t < CHUNK; t++) {
        size_t r = row0 + t;
        float hd = hg[r*2*Dq + d];
        float gg = hg[r*2*Dq + Dq + d];
        float sp = fmaxf(gg, 0.f) + log1pf(expf(-fabsf(gg)));
        float lg = (hd >= 0.f) ? logf(hd + 0.5f) : (hd - log1pf(expf(hd)));
        float c = expf(-sp);
        float v = expf(gg - sp + lg);
        g_c[r*Dq + d] = c;
        g_v[r*Dq + d] = v;
        h = fmaf(c, h, v);
        cp *= c;
    }
    int sidx = (b*NCHUNK + ch)*Dq + d;
    g_Hc[sidx] = h;
    g_Cc[sidx] = cp;
}

__global__ __launch_bounds__(256) void scan2_k()
{
    int d = blockIdx.x * 256 + threadIdx.x;
    int b = blockIdx.z;
    float h = 0.f;
    for (int ch = 0; ch < NCHUNK; ch++) {
        int sidx = (b*NCHUNK + ch)*Dq + d;
        g_Hi[sidx] = h;
        h = fmaf(g_Cc[sidx], h, g_Hc[sidx]);
    }
}

__global__ __launch_bounds__(256) void scan3_k(const float* __restrict__ x1,
                                               float* __restrict__ x2,
                                               float* __restrict__ nh)
{
    int d  = blockIdx.x * 256 + threadIdx.x;
    int ch = blockIdx.y;
    int b  = blockIdx.z;
    size_t row0 = (size_t)b * Lq + (size_t)ch * CHUNK;
    float h = g_Hi[(b*NCHUNK + ch)*Dq + d];
    for (int t = 0; t < CHUNK; t++) {
        size_t r = row0 + t;
        h = fmaf(g_c[r*Dq + d], h, g_v[r*Dq + d]);
        x2[r*Dq + d] = h + x1[r*Dq + d];
    }
    if (ch == NCHUNK - 1) nh[b*Dq + d] = h;
}

// ---------------- launch ----------------
extern "C" void kernel_launch(void* const* d_in, const int* in_sizes, int n_in,
                              void* d_out, int out_size)
{
    const float* x           = (const float*)d_in[0];
    const float* conv_dw_w   = (const float*)d_in[1];
    const float* conv_dw_b   = (const float*)d_in[2];
    const float* conv_pw_w   = (const float*)d_in[3];
    const float* conv_pw_b   = (const float*)d_in[4];
    const float* conv_norm_g = (const float*)d_in[5];
    const float* gru_norm_g  = (const float*)d_in[6];
    const float* gru_w       = (const float*)d_in[7];
    const float* ff_norm_g   = (const float*)d_in[8];
    const float* ff_w1       = (const float*)d_in[9];
    const float* ff_b1       = (const float*)d_in[10];
    const float* ff_w2       = (const float*)d_in[11];
    const float* ff_b2       = (const float*)d_in[12];
    float* out = (float*)d_out;

    float *xn, *y, *x1, *x2, *hg, *h4;
    __half *wh;
    cudaGetSymbolAddress((void**)&xn, g_xn);
    cudaGetSymbolAddress((void**)&y,  g_y);
    cudaGetSymbolAddress((void**)&x1, g_x1);
    cudaGetSymbolAddress((void**)&x2, g_x2);
    cudaGetSymbolAddress((void**)&hg, g_hg);
    cudaGetSymbolAddress((void**)&h4, g_h4);
    cudaGetSymbolAddress((void**)&wh, g_wh);

    __half* xn_h = (__half*)xn;
    __half* y_h  = (__half*)y;
    __half* h4_h = (__half*)h4;
    __half* wh_pw  = wh;                     // 1048576
    __half* wh_gru = wh + 1048576;           // 2097152
    __half* wh_w1  = wh + 3145728;           // 4194304
    __half* wh_w2  = wh + 7340032;           // 4194304

    // weight conversions (f32 -> f16), once per replay
    f2h_k<<<1048576/1024, 256>>>((const float4*)conv_pw_w, (uint2*)wh_pw,  1048576/4);
    f2h_k<<<2097152/1024, 256>>>((const float4*)gru_w,     (uint2*)wh_gru, 2097152/4);
    f2h_k<<<4194304/1024, 256>>>((const float4*)ff_w1,     (uint2*)wh_w1,  4194304/4);
    f2h_k<<<4194304/1024, 256>>>((const float4*)ff_w2,     (uint2*)wh_w2,  4194304/4);

    // 1) conv block
    rmsnorm_dwconv_k<<<Mq, 256>>>(x, conv_norm_g, conv_dw_w, conv_dw_b, y_h);
    gemm_tc<0><<<dim3(Dq/128, Mq/128), 256>>>(y_h, wh_pw, conv_pw_b, x, x1, nullptr, Dq, Dq);

    // 2) gru block
    rmsnorm_h_k<<<Mq, 256>>>(x1, gru_norm_g, xn_h);
    gemm_tc<1><<<dim3(2*Dq/128, Mq/128), 256>>>(xn_h, wh_gru, nullptr, nullptr, hg, nullptr, 2*Dq, Dq);
    scan1_k<<<dim3(Dq/256, NCHUNK, Bq), 256>>>(hg);
    scan2_k<<<dim3(Dq/256, 1, Bq), 256>>>();
    scan3_k<<<dim3(Dq/256, NCHUNK, Bq), 256>>>(x1, x2, out + (size_t)Mq*Dq);

    // 3) ff block
    rmsnorm_h_k<<<Mq, 256>>>(x2, ff_norm_g, xn_h);
    gemm_tc<2><<<dim3(4*Dq/128, Mq/128), 256>>>(xn_h, wh_w1, ff_b1, nullptr, nullptr, h4_h, 4*Dq, Dq);
    gemm_tc<3><<<dim3(Dq/128, Mq/128), 256>>>(h4_h, wh_w2, ff_b2, x2, out, nullptr, Dq, 4*Dq);
}

// round 17
// speedup vs baseline: 3.1844x; 1.0500x over previous
#include <cuda_runtime.h>
#include <cuda_fp16.h>
#include <math.h>
#include <stdint.h>

#define Bq 4
#define Lq 4096
#define Dq 1024
#define Mq (Bq*Lq)              // 16384 rows
#define CHUNK 128
#define NCHUNK (Lq/CHUNK)       // 32

// ---------------- scratch (static device allocations) ----------------
__device__ __align__(256) float g_xn[(size_t)Mq*Dq];   // reused as half buffer
__device__ __align__(256) float g_y [(size_t)Mq*Dq];   // reused as half buffer
__device__ __align__(256) float g_x1[(size_t)Mq*Dq];
__device__ __align__(256) float g_x2[(size_t)Mq*Dq];
__device__ __align__(256) float g_c [(size_t)Mq*Dq];   // used as half buffer
__device__ __align__(256) float g_v [(size_t)Mq*Dq];   // used as half buffer
__device__ __align__(256) float g_hg[(size_t)Mq*2*Dq]; // used as half buffer
__device__ __align__(256) float g_h4[(size_t)Mq*4*Dq]; // used as half buffer
__device__ __align__(256) __half g_wh[11534336];       // fp16 weights: pw|gru|w1|w2
__device__ float g_Hc[Bq*NCHUNK*Dq];
__device__ float g_Cc[Bq*NCHUNK*Dq];
__device__ float g_Hi[Bq*NCHUNK*Dq];

// ---------------- f32 -> f16 weight conversion ----------------
__global__ __launch_bounds__(256) void f2h_k(const float4* __restrict__ in,
                                             uint2* __restrict__ out, int n4)
{
    int i = blockIdx.x * 256 + threadIdx.x;
    if (i >= n4) return;
    float4 v = in[i];
    __half2 h0 = __floats2half2_rn(v.x, v.y);
    __half2 h1 = __floats2half2_rn(v.z, v.w);
    out[i] = make_uint2(*(uint32_t*)&h0, *(uint32_t*)&h1);
}

// ---------------- rmsnorm (fp16 output) ----------------
__global__ __launch_bounds__(256) void rmsnorm_h_k(const float* __restrict__ x,
                                                   const float* __restrict__ g,
                                                   __half* __restrict__ out)
{
    const int row = blockIdx.x;
    const int tid = threadIdx.x;
    const float4* xr = (const float4*)(x + (size_t)row * Dq);
    float4 xv = xr[tid];
    float s = xv.x*xv.x + xv.y*xv.y + xv.z*xv.z + xv.w*xv.w;
    #pragma unroll
    for (int o = 16; o > 0; o >>= 1) s += __shfl_xor_sync(0xffffffffu, s, o);
    __shared__ float red[8];
    if ((tid & 31) == 0) red[tid >> 5] = s;
    __syncthreads();
    if (tid < 32) {
        float t2 = (tid < 8) ? red[tid] : 0.f;
        #pragma unroll
        for (int o = 4; o > 0; o >>= 1) t2 += __shfl_xor_sync(0xffffffffu, t2, o);
        if (tid == 0) red[0] = t2;
    }
    __syncthreads();
    float inv = 32.0f / fmaxf(sqrtf(red[0]), 1e-12f);
    const float4 gv = ((const float4*)g)[tid];
    __half2 h0 = __floats2half2_rn(xv.x * inv * (gv.x + 1.f), xv.y * inv * (gv.y + 1.f));
    __half2 h1 = __floats2half2_rn(xv.z * inv * (gv.z + 1.f), xv.w * inv * (gv.w + 1.f));
    ((uint2*)(out + (size_t)row * Dq))[tid] = make_uint2(*(uint32_t*)&h0, *(uint32_t*)&h1);
}

// ---------------- fused rmsnorm + causal dwconv(K=3) + bias -> fp16 y ----------------
__global__ __launch_bounds__(256) void rmsnorm_dwconv_k(const float* __restrict__ x,
                                                        const float* __restrict__ g,
                                                        const float* __restrict__ wdw,
                                                        const float* __restrict__ bdw,
                                                        __half* __restrict__ yh)
{
    const int row = blockIdx.x;
    const int tid = threadIdx.x;
    const int l = row % Lq;

    float4 xv0 = ((const float4*)(x + (size_t)row * Dq))[tid];
    float4 xv1 = make_float4(0.f,0.f,0.f,0.f);
    float4 xv2 = make_float4(0.f,0.f,0.f,0.f);
    if (l >= 1) xv1 = ((const float4*)(x + (size_t)(row-1) * Dq))[tid];
    if (l >= 2) xv2 = ((const float4*)(x + (size_t)(row-2) * Dq))[tid];

    float s0 = xv0.x*xv0.x + xv0.y*xv0.y + xv0.z*xv0.z + xv0.w*xv0.w;
    float s1 = xv1.x*xv1.x + xv1.y*xv1.y + xv1.z*xv1.z + xv1.w*xv1.w;
    float s2 = xv2.x*xv2.x + xv2.y*xv2.y + xv2.z*xv2.z + xv2.w*xv2.w;
    #pragma unroll
    for (int o = 16; o > 0; o >>= 1) {
        s0 += __shfl_xor_sync(0xffffffffu, s0, o);
        s1 += __shfl_xor_sync(0xffffffffu, s1, o);
        s2 += __shfl_xor_sync(0xffffffffu, s2, o);
    }
    __shared__ float red0[8], red1[8], red2[8], invs[3];
    if ((tid & 31) == 0) { red0[tid>>5]=s0; red1[tid>>5]=s1; red2[tid>>5]=s2; }
    __syncthreads();
    if (tid < 32) {
        float t0 = (tid < 8) ? red0[tid] : 0.f;
        float t1 = (tid < 8) ? red1[tid] : 0.f;
        float t2 = (tid < 8) ? red2[tid] : 0.f;
        #pragma unroll
        for (int o = 4; o > 0; o >>= 1) {
            t0 += __shfl_xor_sync(0xffffffffu, t0, o);
            t1 += __shfl_xor_sync(0xffffffffu, t1, o);
            t2 += __shfl_xor_sync(0xffffffffu, t2, o);
        }
        if (tid == 0) {
            invs[0] = 32.0f / fmaxf(sqrtf(t0), 1e-12f);
            invs[1] = 32.0f / fmaxf(sqrtf(t1), 1e-12f);
            invs[2] = 32.0f / fmaxf(sqrtf(t2), 1e-12f);
        }
    }
    __syncthreads();
    const float inv0 = invs[0], inv1 = invs[1], inv2 = invs[2];
    const float4 gv = ((const float4*)g)[tid];
    const float4* wp = (const float4*)(wdw + tid*12);
    float4 w4a = wp[0], w4b = wp[1], w4c = wp[2];
    const float4 bd = ((const float4*)bdw)[tid];
    float4 y;
    y.x = bd.x + w4a.z*(xv0.x*inv0*(gv.x+1.f)) + w4a.y*(xv1.x*inv1*(gv.x+1.f)) + w4a.x*(xv2.x*inv2*(gv.x+1.f));
    y.y = bd.y + w4b.y*(xv0.y*inv0*(gv.y+1.f)) + w4b.x*(xv1.y*inv1*(gv.y+1.f)) + w4a.w*(xv2.y*inv2*(gv.y+1.f));
    y.z = bd.z + w4c.x*(xv0.z*inv0*(gv.z+1.f)) + w4b.w*(xv1.z*inv1*(gv.z+1.f)) + w4b.z*(xv2.z*inv2*(gv.z+1.f));
    y.w = bd.w + w4c.w*(xv0.w*inv0*(gv.w+1.f)) + w4c.z*(xv1.w*inv1*(gv.w+1.f)) + w4c.y*(xv2.w*inv2*(gv.w+1.f));
    __half2 h0 = __floats2half2_rn(y.x, y.y);
    __half2 h1 = __floats2half2_rn(y.z, y.w);
    ((uint2*)(yh + (size_t)row * Dq))[tid] = make_uint2(*(uint32_t*)&h0, *(uint32_t*)&h1);
}

// ---------------- fp16 GEMM: cp.async 3-stage + ldmatrix + m16n8k16 ----------------
// C[M,N] = A[M,K] * B[N,K]^T, A/B fp16 in gmem, fp32 accum.
// 256 thr, 8 warps, warp tile 64x32, block 128x128, BK=32, STAGES=3, ONE sync/iter.
// MODE 0/3: +bias +res -> f32 C ; MODE 1: plain -> f16 Ch ; MODE 2: +bias gelu -> f16 Ch
#define CPA(dst, src) asm volatile("cp.async.cg.shared.global [%0], [%1], 16;\n" :: "r"(dst), "l"(src))
#define CPC()         asm volatile("cp.async.commit_group;\n" ::: "memory")
#define CPW(n)        asm volatile("cp.async.wait_group %0;\n" :: "n"(n) : "memory")
__device__ __forceinline__ void mma_f16(float* c, const uint32_t* a, const uint32_t* b) {
    asm volatile(
        "mma.sync.aligned.m16n8k16.row.col.f32.f16.f16.f32 "
        "{%0,%1,%2,%3}, {%4,%5,%6,%7}, {%8,%9}, {%0,%1,%2,%3};"
        : "+f"(c[0]), "+f"(c[1]), "+f"(c[2]), "+f"(c[3])
        : "r"(a[0]), "r"(a[1]), "r"(a[2]), "r"(a[3]), "r"(b[0]), "r"(b[1]));
}

template<int MODE>
__global__ __launch_bounds__(256, 2) void gemm_tc(
    const __half* __restrict__ A, const __half* __restrict__ Bm,
    const float* __restrict__ bias, const float* __restrict__ res,
    float* __restrict__ C, __half* __restrict__ Ch, int N_, int K_)
{
    __shared__ __align__(1024) char smem[3*16384];   // stage: A 8KB | B 8KB

    const int tid  = threadIdx.x;
    const int lane = tid & 31;
    const int g    = lane >> 2;
    const int t    = lane & 3;
    const int wid  = tid >> 5;
    const int wm4  = (wid >> 2) * 4;   // 4 m16 tiles
    const int wn4  = (wid & 3) * 4;    // 4 n8 tiles
    const int bm   = blockIdx.y * 128;
    const int bn   = blockIdx.x * 128;
    const uint32_t sb = (uint32_t)__cvta_generic_to_shared(smem);

    // cp.async loader: chunk ci (0..511): row=ci>>2, c16=ci&3
    int arow[2], ac16[2], adst[2];
    #pragma unroll
    for (int p = 0; p < 2; p++) {
        int ci = tid + p*256;
        arow[p] = ci >> 2;
        ac16[p] = ci & 3;
        adst[p] = arow[p]*64 + ((ac16[p] ^ ((arow[p]>>1)&3)) << 4);
    }

    // ldmatrix lane-invariant parts
    const int lar = lane & 15;                 // A tile row
    const int lac = lane >> 4;                 // A k-half
    const int pa_ = (lar >> 1) & 3;
    const int lbr = lane & 7;                  // B tile row
    const int lbc = (lane >> 3) & 1;           // B k-half
    const int pb_ = (lbr >> 1) & 3;

    float acc[4][4][4];
    #pragma unroll
    for (int mi = 0; mi < 4; mi++)
        #pragma unroll
        for (int ni = 0; ni < 4; ni++)
            #pragma unroll
            for (int r = 0; r < 4; r++) acc[mi][ni][r] = 0.f;

    const int niter = K_ >> 5;

    // prologue: stages 0,1
    #pragma unroll
    for (int st = 0; st < 2; st++) {
        int k0 = st << 5;
        #pragma unroll
        for (int p = 0; p < 2; p++) {
            CPA(sb + st*16384 + adst[p],
                A + (size_t)(bm + arow[p]) * K_ + k0 + ac16[p]*8);
            CPA(sb + st*16384 + 8192 + adst[p],
                Bm + (size_t)(bn + arow[p]) * K_ + k0 + ac16[p]*8);
        }
        CPC();
    }

    for (int it = 0; it < niter; it++) {
        const int s = it - (it/3)*3;
        CPW(1);
        __syncthreads();   // single barrier per iter: orders prev compute before overwrite below
        if (it + 2 < niter) {
            int s2 = (it+2) - ((it+2)/3)*3;
            int k0 = (it + 2) << 5;
            #pragma unroll
            for (int p = 0; p < 2; p++) {
                CPA(sb + s2*16384 + adst[p],
                    A + (size_t)(bm + arow[p]) * K_ + k0 + ac16[p]*8);
                CPA(sb + s2*16384 + 8192 + adst[p],
                    Bm + (size_t)(bn + arow[p]) * K_ + k0 + ac16[p]*8);
            }
        }
        CPC();

        const uint32_t abase = sb + s*16384;
        const uint32_t bbase = abase + 8192;
        #pragma unroll
        for (int kk = 0; kk < 2; kk++) {
            const int ca = ((kk*2 + lac) ^ pa_) << 4;
            const int cb = ((kk*2 + lbc) ^ pb_) << 4;
            uint32_t af[4][4];
            #pragma unroll
            for (int mi = 0; mi < 4; mi++) {
                uint32_t ad = abase + (wm4 + mi)*1024 + lar*64 + ca;
                asm volatile("ldmatrix.sync.aligned.m8n8.x4.shared.b16 {%0,%1,%2,%3}, [%4];"
                    : "=r"(af[mi][0]), "=r"(af[mi][1]), "=r"(af[mi][2]), "=r"(af[mi][3])
                    : "r"(ad));
            }
            uint32_t bf[4][2];
            #pragma unroll
            for (int ni = 0; ni < 4; ni++) {
                uint32_t bd = bbase + (wn4 + ni)*512 + lbr*64 + cb;
                asm volatile("ldmatrix.sync.aligned.m8n8.x2.shared.b16 {%0,%1}, [%2];"
                    : "=r"(bf[ni][0]), "=r"(bf[ni][1])
                    : "r"(bd));
            }
            #pragma unroll
            for (int mi = 0; mi < 4; mi++)
                #pragma unroll
                for (int ni = 0; ni < 4; ni++)
                    mma_f16(acc[mi][ni], af[mi], bf[ni]);
        }
        // no trailing barrier: next iter's top barrier provides the ordering
    }

    // ---------------- epilogue ----------------
    #pragma unroll
    for (int mi = 0; mi < 4; mi++) {
        #pragma unroll
        for (int ni = 0; ni < 4; ni++) {
            int row0 = bm + (wm4 + mi)*16 + g;
            int col  = bn + (wn4 + ni)*8 + 2*t;
            #pragma unroll
            for (int h = 0; h < 2; h++) {
                int row = row0 + h*8;
                float v0 = acc[mi][ni][2*h + 0];
                float v1 = acc[mi][ni][2*h + 1];
                if (MODE == 0 || MODE == 3) {
                    v0 += bias[col]   + res[(size_t)row * N_ + col];
                    v1 += bias[col+1] + res[(size_t)row * N_ + col + 1];
                    *(float2*)(C + (size_t)row * N_ + col) = make_float2(v0, v1);
                } else if (MODE == 2) {
                    v0 += bias[col];
                    v1 += bias[col+1];
                    v0 = 0.5f * v0 * (1.f + erff(v0 * 0.70710678118654752f));
                    v1 = 0.5f * v1 * (1.f + erff(v1 * 0.70710678118654752f));
                    __half2 hv = __floats2half2_rn(v0, v1);
                    *(uint32_t*)(Ch + (size_t)row * N_ + col) = *(uint32_t*)&hv;
                } else {   // MODE 1: plain -> fp16
                    __half2 hv = __floats2half2_rn(v0, v1);
                    *(uint32_t*)(Ch + (size_t)row * N_ + col) = *(uint32_t*)&hv;
                }
            }
        }
    }
}

// ---------------- minGRU chunked scan (fp16 hg/c/v, f32 accumulation) ----------------
__global__ __launch_bounds__(256) void scan1_k(const __half* __restrict__ hg,
                                               __half* __restrict__ ch,
                                               __half* __restrict__ vh)
{
    int d  = blockIdx.x * 256 + threadIdx.x;
    int chk = blockIdx.y;
    int b  = blockIdx.z;
    size_t row0 = (size_t)b * Lq + (size_t)chk * CHUNK;
    float h = 0.f, cp = 1.f;
    for (int t = 0; t < CHUNK; t++) {
        size_t r = row0 + t;
        float hd = __half2float(hg[r*2*Dq + d]);
        float gg = __half2float(hg[r*2*Dq + Dq + d]);
        float sp = fmaxf(gg, 0.f) + log1pf(expf(-fabsf(gg)));
        float lg = (hd >= 0.f) ? logf(hd + 0.5f) : (hd - log1pf(expf(hd)));
        float c = expf(-sp);
        float v = expf(gg - sp + lg);
        ch[r*Dq + d] = __float2half_rn(c);
        vh[r*Dq + d] = __float2half_rn(v);
        h = fmaf(c, h, v);
        cp *= c;
    }
    int sidx = (b*NCHUNK + chk)*Dq + d;
    g_Hc[sidx] = h;
    g_Cc[sidx] = cp;
}

__global__ __launch_bounds__(256) void scan2_k()
{
    int d = blockIdx.x * 256 + threadIdx.x;
    int b = blockIdx.z;
    float h = 0.f;
    for (int ch = 0; ch < NCHUNK; ch++) {
        int sidx = (b*NCHUNK + ch)*Dq + d;
        g_Hi[sidx] = h;
        h = fmaf(g_Cc[sidx], h, g_Hc[sidx]);
    }
}

__global__ __launch_bounds__(256) void scan3_k(const __half* __restrict__ ch,
                                               const __half* __restrict__ vh,
                                               const float* __restrict__ x1,
                                               float* __restrict__ x2,
                                               float* __restrict__ nh)
{
    int d  = blockIdx.x * 256 + threadIdx.x;
    int chk = blockIdx.y;
    int b  = blockIdx.z;
    size_t row0 = (size_t)b * Lq + (size_t)chk * CHUNK;
    float h = g_Hi[(b*NCHUNK + chk)*Dq + d];
    for (int t = 0; t < CHUNK; t++) {
        size_t r = row0 + t;
        h = fmaf(__half2float(ch[r*Dq + d]), h, __half2float(vh[r*Dq + d]));
        x2[r*Dq + d] = h + x1[r*Dq + d];
    }
    if (chk == NCHUNK - 1) nh[b*Dq + d] = h;
}

// ---------------- launch ----------------
extern "C" void kernel_launch(void* const* d_in, const int* in_sizes, int n_in,
                              void* d_out, int out_size)
{
    const float* x           = (const float*)d_in[0];
    const float* conv_dw_w   = (const float*)d_in[1];
    const float* conv_dw_b   = (const float*)d_in[2];
    const float* conv_pw_w   = (const float*)d_in[3];
    const float* conv_pw_b   = (const float*)d_in[4];
    const float* conv_norm_g = (const float*)d_in[5];
    const float* gru_norm_g  = (const float*)d_in[6];
    const float* gru_w       = (const float*)d_in[7];
    const float* ff_norm_g   = (const float*)d_in[8];
    const float* ff_w1       = (const float*)d_in[9];
    const float* ff_b1       = (const float*)d_in[10];
    const float* ff_w2       = (const float*)d_in[11];
    const float* ff_b2       = (const float*)d_in[12];
    float* out = (float*)d_out;

    float *xn, *y, *x1, *x2, *hg, *h4, *cbuf, *vbuf;
    __half *wh;
    cudaGetSymbolAddress((void**)&xn, g_xn);
    cudaGetSymbolAddress((void**)&y,  g_y);
    cudaGetSymbolAddress((void**)&x1, g_x1);
    cudaGetSymbolAddress((void**)&x2, g_x2);
    cudaGetSymbolAddress((void**)&hg, g_hg);
    cudaGetSymbolAddress((void**)&h4, g_h4);
    cudaGetSymbolAddress((void**)&cbuf, g_c);
    cudaGetSymbolAddress((void**)&vbuf, g_v);
    cudaGetSymbolAddress((void**)&wh, g_wh);

    __half* xn_h = (__half*)xn;
    __half* y_h  = (__half*)y;
    __half* h4_h = (__half*)h4;
    __half* hg_h = (__half*)hg;
    __half* c_h  = (__half*)cbuf;
    __half* v_h  = (__half*)vbuf;
    __half* wh_pw  = wh;                     // 1048576
    __half* wh_gru = wh + 1048576;           // 2097152
    __half* wh_w1  = wh + 3145728;           // 4194304
    __half* wh_w2  = wh + 7340032;           // 4194304

    // weight conversions (f32 -> f16), once per replay
    f2h_k<<<1048576/1024, 256>>>((const float4*)conv_pw_w, (uint2*)wh_pw,  1048576/4);
    f2h_k<<<2097152/1024, 256>>>((const float4*)gru_w,     (uint2*)wh_gru, 2097152/4);
    f2h_k<<<4194304/1024, 256>>>((const float4*)ff_w1,     (uint2*)wh_w1,  4194304/4);
    f2h_k<<<4194304/1024, 256>>>((const float4*)ff_w2,     (uint2*)wh_w2,  4194304/4);

    // 1) conv block
    rmsnorm_dwconv_k<<<Mq, 256>>>(x, conv_norm_g, conv_dw_w, conv_dw_b, y_h);
    gemm_tc<0><<<dim3(Dq/128, Mq/128), 256>>>(y_h, wh_pw, conv_pw_b, x, x1, nullptr, Dq, Dq);

    // 2) gru block
    rmsnorm_h_k<<<Mq, 256>>>(x1, gru_norm_g, xn_h);
    gemm_tc<1><<<dim3(2*Dq/128, Mq/128), 256>>>(xn_h, wh_gru, nullptr, nullptr, nullptr, hg_h, 2*Dq, Dq);
    scan1_k<<<dim3(Dq/256, NCHUNK, Bq), 256>>>(hg_h, c_h, v_h);
    scan2_k<<<dim3(Dq/256, 1, Bq), 256>>>();
    scan3_k<<<dim3(Dq/256, NCHUNK, Bq), 256>>>(c_h, v_h, x1, x2, out + (size_t)Mq*Dq);

    // 3) ff block
    rmsnorm_h_k<<<Mq, 256>>>(x2, ff_norm_g, xn_h);
    gemm_tc<2><<<dim3(4*Dq/128, Mq/128), 256>>>(xn_h, wh_w1, ff_b1, nullptr, nullptr, h4_h, 4*Dq, Dq);
    gemm_tc<3><<<dim3(Dq/128, Mq/128), 256>>>(h4_h, wh_w2, ff_b2, x2, out, nullptr, Dq, 4*Dq);
}